// round 13
// baseline (speedup 1.0000x reference)
#include <cuda_runtime.h>
#include <cuda_fp16.h>
#include <mma.h>
#include <math.h>

using namespace nvcuda;

#define NN 10000
#define EE 320000
#define INF 256
#define HID 128
#define HEADS 4
#define PAD 32        // counter stride in ints -> one 128B line per counter
#define CAP 96        // max in-degree bucket capacity
#define NB 592        // 148 SMs x 4 blocks co-resident (launch_bounds enforced)
#define NT 256
#define NTILE 313     // ceil(NN/32) gemm row tiles

// ---------------- scratch (static device globals; no allocs) ----------------
__device__ int      g_incnt[NN * PAD];
__device__ int      g_outcnt[NN * PAD];
__device__ int      g_esrc[NN * CAP];
__device__ float    g_doutf[NN];
__device__ __half   g_w1h[INF * HID];
__device__ __half   g_w2h[HID * HID];
__device__ __half   g_t0h[NN * HID];
__device__ __half   g_h1h[NN * HID];
__device__ float4   g_el4[NN];
__device__ float4   g_er4[NN];
__device__ float4   g_w4[NN];
__device__ float    g_M[HID][12];
__device__ float    g_cbg;
__device__ float    g_y[NN];
__device__ unsigned g_bar;   // phase barrier counter (self-reset each launch)
__device__ unsigned g_ack;   // completion ack counter  (self-reset each launch)

__device__ __forceinline__ float inv_sqrt_deg(int cnt) {
    return rsqrtf(fmaxf((float)cnt, 1.f));
}

// grid barrier: all NB blocks arrive; target = phase * NB (monotonic)
__device__ __forceinline__ void gbar(unsigned target) {
    __syncthreads();
    if (threadIdx.x == 0) {
        __threadfence();
        atomicAdd(&g_bar, 1u);
        while (atomicAdd(&g_bar, 0u) < target) __nanosleep(64);
        __threadfence();
    }
    __syncthreads();
}

// ---------------- gemm tile: 32x128, BK=32, 256 thr, WMMA fp16 ----------------
template<int K, int SRC>
__device__ __forceinline__ void gemm_tile(const float* __restrict__ Aext,
                                          int tile, char* smraw) {
    constexpr int NIT = K / 32;
    const __half* __restrict__ Wh = (SRC == 0) ? g_w1h : g_w2h;
    __half (*As)[40]  = reinterpret_cast<__half(*)[40]>(smraw);
    __half (*Bs)[136] = reinterpret_cast<__half(*)[136]>(smraw + 2560);
    float  (*Cs)[128] = reinterpret_cast<float(*)[128]>(smraw);

    int tid = threadIdx.x;
    int warp = tid >> 5;
    int wr = warp & 1, wc = warp >> 1;
    int row0 = tile * 32;

    int ar = tid >> 3, akq = (tid & 7) * 4;
    int bkr = tid >> 3, bcb = (tid & 7) * 16;
    bool arow_ok = (row0 + ar) < NN;

    wmma::fragment<wmma::accumulator, 16, 16, 16, float> c0, c1;
    wmma::fill_fragment(c0, 0.f);
    wmma::fill_fragment(c1, 0.f);

    float4 aP = make_float4(0.f, 0.f, 0.f, 0.f);
    uint2  aPh = make_uint2(0, 0);
    uint4  bP0, bP1;

    auto LOAD = [&](int k0) {
        if (SRC == 0) {
            aP = arow_ok ? *(const float4*)(Aext + (size_t)(row0 + ar) * K + k0 + akq)
                         : make_float4(0.f, 0.f, 0.f, 0.f);
        } else {
            aPh = arow_ok ? *(const uint2*)(g_h1h + (size_t)(row0 + ar) * K + k0 + akq)
                          : make_uint2(0, 0);
        }
        const uint4* wp = (const uint4*)(Wh + (size_t)(k0 + bkr) * HID + bcb);
        bP0 = wp[0];
        bP1 = wp[1];
    };

    LOAD(0);
#pragma unroll
    for (int it = 0; it < NIT; it++) {
        if (it) __syncthreads();
        if (SRC == 0) {
            __half2 h0 = __floats2half2_rn(aP.x, aP.y);
            __half2 h1 = __floats2half2_rn(aP.z, aP.w);
            uint2 u; u.x = *(unsigned*)&h0; u.y = *(unsigned*)&h1;
            *(uint2*)&As[ar][akq] = u;
        } else {
            *(uint2*)&As[ar][akq] = aPh;
        }
        *(uint4*)&Bs[bkr][bcb] = bP0;
        *(uint4*)&Bs[bkr][bcb + 8] = bP1;
        __syncthreads();
        if (it + 1 < NIT) LOAD((it + 1) * 32);
#pragma unroll
        for (int kk = 0; kk < 32; kk += 16) {
            wmma::fragment<wmma::matrix_a, 16, 16, 16, __half, wmma::row_major> a;
            wmma::fragment<wmma::matrix_b, 16, 16, 16, __half, wmma::row_major> b0, b1;
            wmma::load_matrix_sync(a, &As[wr * 16][kk], 40);
            wmma::load_matrix_sync(b0, &Bs[kk][wc * 32], 136);
            wmma::load_matrix_sync(b1, &Bs[kk][wc * 32 + 16], 136);
            wmma::mma_sync(c0, a, b0, c0);
            wmma::mma_sync(c1, a, b1, c1);
        }
    }
    __syncthreads();
    wmma::store_matrix_sync(&Cs[wr * 16][wc * 32], c0, 128, wmma::mem_row_major);
    wmma::store_matrix_sync(&Cs[wr * 16][wc * 32 + 16], c1, 128, wmma::mem_row_major);
    __syncthreads();
    {
        int r = tid >> 3, cb = (tid & 7) * 16;
        int row = row0 + r;
        if (row < NN) {
            __half2 buf[8];
#pragma unroll
            for (int q = 0; q < 8; q++)
                buf[q] = __floats2half2_rn(Cs[r][cb + q * 2], Cs[r][cb + q * 2 + 1]);
            uint4* op = (uint4*)(g_t0h + (size_t)row * HID + cb);
            const uint4* bp = (const uint4*)buf;
            op[0] = bp[0]; op[1] = bp[1];
        }
    }
    __syncthreads();    // smem reuse safety before next phase
}

// ---------------- agg helper: warp gathers+sums t0 rows ----------------------
template<bool EDGESCALE>
__device__ __forceinline__ float4 agg_row(int n, int lane, const float* b) {
    int cnt = g_incnt[n * PAD];
    int m = min(cnt, CAP);
    const int* row = g_esrc + n * CAP;
    float4 acc = make_float4(0.f, 0.f, 0.f, 0.f);
#pragma unroll 4
    for (int j = 0; j < m; j++) {
        int s = row[j];
        float ds = EDGESCALE ? g_doutf[s] : 1.f;
        const __half2* p = (const __half2*)(g_t0h + (size_t)s * HID + lane * 4);
        float2 v0 = __half22float2(p[0]);
        float2 v1 = __half22float2(p[1]);
        if (EDGESCALE) {
            acc.x = fmaf(ds, v0.x, acc.x); acc.y = fmaf(ds, v0.y, acc.y);
            acc.z = fmaf(ds, v1.x, acc.z); acc.w = fmaf(ds, v1.y, acc.w);
        } else {
            acc.x += v0.x; acc.y += v0.y; acc.z += v1.x; acc.w += v1.y;
        }
    }
    float din = inv_sqrt_deg(cnt);
    float4 bb = *(const float4*)(b + lane * 4);
    float4 o;
    o.x = fmaxf(acc.x * din + bb.x, 0.f);
    o.y = fmaxf(acc.y * din + bb.y, 0.f);
    o.z = fmaxf(acc.z * din + bb.z, 0.f);
    o.w = fmaxf(acc.w * din + bb.w, 0.f);
    return o;
}

// ---------------- THE mega kernel ----------------
__global__ void __launch_bounds__(256, 4) k_mega(
    const float* __restrict__ features,
    const int* __restrict__ src, const int* __restrict__ dst,
    const float* __restrict__ W1, const float* __restrict__ b1,
    const float* __restrict__ W2, const float* __restrict__ b2,
    const float* __restrict__ W3, const float* __restrict__ b3,
    const float* __restrict__ Wg, const float* __restrict__ attn_l,
    const float* __restrict__ attn_r, const float* __restrict__ bg,
    float* __restrict__ out)
{
    __shared__ __align__(16) char smraw[16384];
    int tid = blockIdx.x * NT + threadIdx.x;
    int lane = threadIdx.x & 31;
    int gwarp = blockIdx.x * 8 + (threadIdx.x >> 5);

    // ========== P0: zero counters, convert weights, M dots, cbg ==========
    if (tid < NN) { g_incnt[tid * PAD] = 0; g_outcnt[tid * PAD] = 0; }
    {
        const int NQ = (INF * HID + HID * HID) / 4;   // 12288 quads
        if (tid < NQ) {
            int i4 = tid * 4;
            float4 v;
            __half* dstp;
            if (i4 < INF * HID) { v = *(const float4*)(W1 + i4); dstp = g_w1h + i4; }
            else { v = *(const float4*)(W2 + i4 - INF * HID); dstp = g_w2h + (i4 - INF * HID); }
            __half2 h0 = __floats2half2_rn(v.x, v.y);
            __half2 h1 = __floats2half2_rn(v.z, v.w);
            uint2 u; u.x = *(unsigned*)&h0; u.y = *(unsigned*)&h1;
            *(uint2*)dstp = u;
        }
    }
    if (gwarp < 512) {
        int k = gwarp >> 2, h = gwarp & 3;
        float sl = 0.f, sr = 0.f, sw = 0.f;
        for (int i = lane; i < HID; i += 32) {
            float wv = Wg[(size_t)k * (HEADS * HID) + h * HID + i];
            sl += wv * attn_l[h * HID + i];
            sr += wv * attn_r[h * HID + i];
            sw += wv * W3[i];
        }
#pragma unroll
        for (int o = 16; o; o >>= 1) {
            sl += __shfl_xor_sync(0xFFFFFFFFu, sl, o);
            sr += __shfl_xor_sync(0xFFFFFFFFu, sr, o);
            sw += __shfl_xor_sync(0xFFFFFFFFu, sw, o);
        }
        if (!lane) { g_M[k][h] = sl; g_M[k][4 + h] = sr; g_M[k][8 + h] = sw; }
    } else if (gwarp == 512) {
        float s = 0.f;
        for (int i = lane; i < HEADS * HID; i += 32) s += bg[i] * W3[i & (HID - 1)];
#pragma unroll
        for (int o = 16; o; o >>= 1) s += __shfl_xor_sync(0xFFFFFFFFu, s, o);
        if (!lane) g_cbg = s;
    }
    gbar(1u * NB);

    // ========== P1: CSR build (blocks >= NTILE) || GEMM1 (blocks < NTILE) ====
    if (blockIdx.x < NTILE) {
        gemm_tile<INF, 0>(features, blockIdx.x, smraw);
    } else {
        const int bstride = (NB - NTILE) * NT;   // 71424
        for (int e = (blockIdx.x - NTILE) * NT + threadIdx.x; e < EE; e += bstride) {
            int s = src[e], d = dst[e];
            atomicAdd(&g_outcnt[s * PAD], 1);
            int slot = atomicAdd(&g_incnt[d * PAD], 1);
            if (slot < CAP) g_esrc[d * CAP + slot] = s;
        }
    }
    gbar(2u * NB);

    // ========== P2: dout micro-phase ==========
    if (tid < NN) g_doutf[tid] = inv_sqrt_deg(g_outcnt[tid * PAD]);
    gbar(3u * NB);

    // ========== P3: agg1 -> h1h ==========
    for (int n = gwarp; n < NN; n += NB * 8) {
        float4 o = agg_row<true>(n, lane, b1);
        float dn = g_doutf[n];
        __half2* hp = (__half2*)(g_h1h + (size_t)n * HID + lane * 4);
        hp[0] = __floats2half2_rn(o.x * dn, o.y * dn);
        hp[1] = __floats2half2_rn(o.z * dn, o.w * dn);
    }
    gbar(4u * NB);

    // ========== P4: GEMM2 ==========
    if (blockIdx.x < NTILE) gemm_tile<HID, 1>(nullptr, blockIdx.x, smraw);
    gbar(5u * NB);

    // ========== P5: agg2 + el/er/w projection ==========
    for (int n = gwarp; n < NN; n += NB * 8) {
        float4 o = agg_row<false>(n, lane, b2);
        float hr[4] = {o.x, o.y, o.z, o.w};
        float dots[12];
#pragma unroll
        for (int j = 0; j < 12; j++) {
            float s = 0.f;
#pragma unroll
            for (int i = 0; i < 4; i++) s = fmaf(hr[i], g_M[lane * 4 + i][j], s);
            dots[j] = s;
        }
#pragma unroll
        for (int off = 16; off; off >>= 1)
#pragma unroll
            for (int j = 0; j < 12; j++)
                dots[j] += __shfl_xor_sync(0xFFFFFFFFu, dots[j], off);
        if (!lane) {
            g_el4[n] = make_float4(dots[0], dots[1], dots[2], dots[3]);
            g_er4[n] = make_float4(dots[4], dots[5], dots[6], dots[7]);
            g_w4[n]  = make_float4(dots[8], dots[9], dots[10], dots[11]);
        }
    }
    gbar(6u * NB);

    // ========== P6: scalar GAT -> g_y ==========
    for (int d = gwarp; d < NN; d += NB * 8) {
        int cnt = min(g_incnt[d * PAD], CAP);
        const int* row = g_esrc + d * CAP;
        float4 er = g_er4[d];
        float erh[4] = {er.x, er.y, er.z, er.w};
        float m[4], den[4], aw[4];
#pragma unroll
        for (int h = 0; h < 4; h++) { m[h] = -INFINITY; den[h] = 0.f; aw[h] = 0.f; }
        for (int j = lane; j < cnt; j += 32) {
            int s = row[j];
            float4 el = g_el4[s];
            float4 wv = g_w4[s];
            float elh[4] = {el.x, el.y, el.z, el.w};
            float wh[4] = {wv.x, wv.y, wv.z, wv.w};
#pragma unroll
            for (int h = 0; h < 4; h++) {
                float e = elh[h] + erh[h];
                e = e > 0.f ? e : 0.2f * e;
                float mn = fmaxf(m[h], e);
                float sc = __expf(m[h] - mn);
                float p  = __expf(e - mn);
                den[h] = den[h] * sc + p;
                aw[h]  = aw[h] * sc + p * wh[h];
                m[h] = mn;
            }
        }
#pragma unroll
        for (int off = 16; off; off >>= 1) {
#pragma unroll
            for (int h = 0; h < 4; h++) {
                float m2 = __shfl_xor_sync(0xFFFFFFFFu, m[h], off);
                float d2 = __shfl_xor_sync(0xFFFFFFFFu, den[h], off);
                float a2 = __shfl_xor_sync(0xFFFFFFFFu, aw[h], off);
                float mn = fmaxf(m[h], m2);
                float s1 = (m[h] == mn) ? 1.f : __expf(m[h] - mn);
                float s2 = (m2 == mn) ? 1.f : __expf(m2 - mn);
                den[h] = den[h] * s1 + d2 * s2;
                aw[h]  = aw[h] * s1 + a2 * s2;
                m[h] = mn;
            }
        }
        if (!lane) {
            float s = g_cbg;
#pragma unroll
            for (int h = 0; h < 4; h++) s += (den[h] > 0.f) ? (aw[h] / den[h]) : 0.f;
            g_y[d] = 0.25f * s * g_doutf[d];
        }
    }
    gbar(7u * NB);

    // ========== P7: final conv + sigmoid ==========
    for (int n = gwarp; n < NN; n += NB * 8) {
        int cnt = g_incnt[n * PAD];
        int mm = min(cnt, CAP);
        const int* row = g_esrc + n * CAP;
        float s = 0.f;
        for (int j = lane; j < mm; j += 32) s += g_y[row[j]];
#pragma unroll
        for (int o = 16; o; o >>= 1) s += __shfl_xor_sync(0xFFFFFFFFu, s, o);
        if (!lane) {
            float v = s * inv_sqrt_deg(cnt) + b3[0];
            out[n] = 1.f / (1.f + __expf(-v));
        }
    }

    // self-reset for next launch: last block to ack zeroes the counters.
    __syncthreads();
    if (threadIdx.x == 0) {
        unsigned old = atomicAdd(&g_ack, 1u);
        if (old == NB - 1) { g_bar = 0u; g_ack = 0u; __threadfence(); }
    }
}

// ---------------- launch: ONE kernel ----------------
extern "C" void kernel_launch(void* const* d_in, const int* in_sizes, int n_in,
                              void* d_out, int out_size) {
    const float* features = (const float*)d_in[0];
    const int*   src      = (const int*)d_in[1];
    const int*   dst      = (const int*)d_in[2];
    const float* W1       = (const float*)d_in[3];
    const float* b1       = (const float*)d_in[4];
    const float* W2       = (const float*)d_in[5];
    const float* b2       = (const float*)d_in[6];
    const float* W3       = (const float*)d_in[7];
    const float* b3       = (const float*)d_in[8];
    const float* Wg       = (const float*)d_in[9];
    const float* attn_l   = (const float*)d_in[10];
    const float* attn_r   = (const float*)d_in[11];
    const float* bg       = (const float*)d_in[12];
    float* out = (float*)d_out;

    k_mega<<<NB, NT>>>(features, src, dst, W1, b1, W2, b2, W3, b3,
                       Wg, attn_l, attn_r, bg, out);
}

// round 14
// speedup vs baseline: 1.0025x; 1.0025x over previous
#include <cuda_runtime.h>
#include <cuda_fp16.h>
#include <mma.h>
#include <math.h>

using namespace nvcuda;

#define NN 10000
#define EE 320000
#define INF 256
#define HID 128
#define HEADS 4
#define PAD 32      // counter stride in ints -> one 128B line per counter
#define CAP 96      // max in-degree bucket capacity (Poisson(32): P(>96) ~ 1e-37)
#define GF_BLOCKS 592   // 148 SMs x 4 blocks: co-resident => spin barrier safe

// ---------------- scratch (static device globals; no allocs) ----------------
__device__ int      g_incnt[NN * PAD];
__device__ int      g_outcnt[NN * PAD];
__device__ int      g_esrc[NN * CAP];    // bucketed CSR-by-dst
__device__ float    g_doutf[NN];         // rsqrt(max(outdeg,1)) precomputed
__device__ __half   g_w1h[INF * HID];    // W1 fp16 (converted once)
__device__ __half   g_w2h[HID * HID];    // W2 fp16 (converted once)
__device__ __half   g_t0h[NN * HID];     // gemm output (pre-agg), fp16
__device__ __half   g_h1h[NN * HID];     // relu(conv1)*dout, fp16 (gemm2 input)
__device__ float4   g_el4[NN];
__device__ float4   g_er4[NN];
__device__ float4   g_w4[NN];
__device__ float    g_M[HID][12];        // folded Wg·attn_l | Wg·attn_r | Wg·W3
__device__ float    g_cbg;
__device__ float    g_y[NN];
__device__ unsigned g_bar;               // grid barrier counter (reset in k_prep)

__device__ __forceinline__ float inv_sqrt_deg(int cnt) {
    return rsqrtf(fmaxf((float)cnt, 1.f));
}

// ---------------- weight fp32->fp16 conversion ----------------
// W1 on stream 0 (needed by gemm1); W2 on s1 (hidden under gemm1).
__global__ void __launch_bounds__(256) k_wcvt1(const float* __restrict__ W1) {
    int i4 = (blockIdx.x * 256 + threadIdx.x) * 4;
    float4 v = *(const float4*)(W1 + i4);
    __half2 h0 = __floats2half2_rn(v.x, v.y);
    __half2 h1 = __floats2half2_rn(v.z, v.w);
    uint2 u; u.x = *(unsigned*)&h0; u.y = *(unsigned*)&h1;
    *(uint2*)(g_w1h + i4) = u;
}
__global__ void __launch_bounds__(256) k_wcvt2(const float* __restrict__ W2) {
    int i4 = (blockIdx.x * 256 + threadIdx.x) * 4;
    float4 v = *(const float4*)(W2 + i4);
    __half2 h0 = __floats2half2_rn(v.x, v.y);
    __half2 h1 = __floats2half2_rn(v.z, v.w);
    uint2 u; u.x = *(unsigned*)&h0; u.y = *(unsigned*)&h1;
    *(uint2*)(g_w2h + i4) = u;
}

// ---------------- precompute M, cbg + zero padded counters + reset barrier ---
__global__ void __launch_bounds__(256) k_prep(const float* __restrict__ Wg,
                                              const float* __restrict__ attn_l,
                                              const float* __restrict__ attn_r,
                                              const float* __restrict__ W3,
                                              const float* __restrict__ bg) {
    int lane = threadIdx.x & 31;
    if (blockIdx.x >= 65) {
        int idx = (blockIdx.x - 65) * 256 + threadIdx.x;
        if (idx < NN) { g_incnt[idx * PAD] = 0; g_outcnt[idx * PAD] = 0; }
        return;
    }
    if (blockIdx.x == 64) {
        if (threadIdx.x == 32) g_bar = 0u;
        if (threadIdx.x < 32) {
            float s = 0.f;
            for (int i = lane; i < HEADS * HID; i += 32) s += bg[i] * W3[i & (HID - 1)];
#pragma unroll
            for (int o = 16; o; o >>= 1) s += __shfl_xor_sync(0xFFFFFFFFu, s, o);
            if (!lane) g_cbg = s;
        }
        return;
    }
    int gw = blockIdx.x * 8 + (threadIdx.x >> 5);
    int k = gw >> 2, h = gw & 3;
    float sl = 0.f, sr = 0.f, sw = 0.f;
    for (int i = lane; i < HID; i += 32) {
        float wv = Wg[(size_t)k * (HEADS * HID) + h * HID + i];
        sl += wv * attn_l[h * HID + i];
        sr += wv * attn_r[h * HID + i];
        sw += wv * W3[i];
    }
#pragma unroll
    for (int o = 16; o; o >>= 1) {
        sl += __shfl_xor_sync(0xFFFFFFFFu, sl, o);
        sr += __shfl_xor_sync(0xFFFFFFFFu, sr, o);
        sw += __shfl_xor_sync(0xFFFFFFFFu, sw, o);
    }
    if (!lane) { g_M[k][h] = sl; g_M[k][4 + h] = sr; g_M[k][8 + h] = sw; }
}

// ---------------- one-pass bucketed CSR build ----------------
__global__ void k_build(const int* __restrict__ src, const int* __restrict__ dst) {
    int e = blockIdx.x * blockDim.x + threadIdx.x;
    if (e >= EE) return;
    int s = src[e], d = dst[e];
    atomicAdd(&g_outcnt[s * PAD], 1);
    int slot = atomicAdd(&g_incnt[d * PAD], 1);
    if (slot < CAP) g_esrc[d * CAP + slot] = s;
}

__global__ void k_dout() {
    int n = blockIdx.x * blockDim.x + threadIdx.x;
    if (n < NN) g_doutf[n] = inv_sqrt_deg(g_outcnt[n * PAD]);
}

// ---------------- WMMA fp16 GEMM: 32x128 tile, BK=32, 256 thr ----------------
template<int K, int SRC>
__global__ void __launch_bounds__(256) k_gemm_mma(const float* __restrict__ Aext) {
    constexpr int NIT = K / 32;
    const __half* __restrict__ Wh = (SRC == 0) ? g_w1h : g_w2h;
    __shared__ __align__(16) char smraw[16384];
    __half (*As)[40]  = reinterpret_cast<__half(*)[40]>(smraw);
    __half (*Bs)[136] = reinterpret_cast<__half(*)[136]>(smraw + 2560);
    float  (*Cs)[128] = reinterpret_cast<float(*)[128]>(smraw);

    int tid = threadIdx.x;
    int warp = tid >> 5;
    int wr = warp & 1, wc = warp >> 1;
    int row0 = blockIdx.x * 32;

    int ar = tid >> 3, akq = (tid & 7) * 4;
    int bkr = tid >> 3, bcb = (tid & 7) * 16;
    bool arow_ok = (row0 + ar) < NN;

    wmma::fragment<wmma::accumulator, 16, 16, 16, float> c0, c1;
    wmma::fill_fragment(c0, 0.f);
    wmma::fill_fragment(c1, 0.f);

    float4 aP = make_float4(0.f, 0.f, 0.f, 0.f);
    uint2  aPh = make_uint2(0, 0);
    uint4  bP0, bP1;

    auto LOAD = [&](int k0) {
        if (SRC == 0) {
            aP = arow_ok ? *(const float4*)(Aext + (size_t)(row0 + ar) * K + k0 + akq)
                         : make_float4(0.f, 0.f, 0.f, 0.f);
        } else {
            aPh = arow_ok ? *(const uint2*)(g_h1h + (size_t)(row0 + ar) * K + k0 + akq)
                          : make_uint2(0, 0);
        }
        const uint4* wp = (const uint4*)(Wh + (size_t)(k0 + bkr) * HID + bcb);
        bP0 = wp[0];
        bP1 = wp[1];
    };

    LOAD(0);
#pragma unroll
    for (int it = 0; it < NIT; it++) {
        if (it) __syncthreads();
        if (SRC == 0) {
            __half2 h0 = __floats2half2_rn(aP.x, aP.y);
            __half2 h1 = __floats2half2_rn(aP.z, aP.w);
            uint2 u; u.x = *(unsigned*)&h0; u.y = *(unsigned*)&h1;
            *(uint2*)&As[ar][akq] = u;
        } else {
            *(uint2*)&As[ar][akq] = aPh;
        }
        *(uint4*)&Bs[bkr][bcb] = bP0;
        *(uint4*)&Bs[bkr][bcb + 8] = bP1;
        __syncthreads();
        if (it + 1 < NIT) LOAD((it + 1) * 32);
#pragma unroll
        for (int kk = 0; kk < 32; kk += 16) {
            wmma::fragment<wmma::matrix_a, 16, 16, 16, __half, wmma::row_major> a;
            wmma::fragment<wmma::matrix_b, 16, 16, 16, __half, wmma::row_major> b0, b1;
            wmma::load_matrix_sync(a, &As[wr * 16][kk], 40);
            wmma::load_matrix_sync(b0, &Bs[kk][wc * 32], 136);
            wmma::load_matrix_sync(b1, &Bs[kk][wc * 32 + 16], 136);
            wmma::mma_sync(c0, a, b0, c0);
            wmma::mma_sync(c1, a, b1, c1);
        }
    }
    __syncthreads();
    wmma::store_matrix_sync(&Cs[wr * 16][wc * 32], c0, 128, wmma::mem_row_major);
    wmma::store_matrix_sync(&Cs[wr * 16][wc * 32 + 16], c1, 128, wmma::mem_row_major);
    __syncthreads();
    {
        int r = tid >> 3, cb = (tid & 7) * 16;
        int row = row0 + r;
        if (row < NN) {
            __half2 buf[8];
#pragma unroll
            for (int q = 0; q < 8; q++)
                buf[q] = __floats2half2_rn(Cs[r][cb + q * 2], Cs[r][cb + q * 2 + 1]);
            uint4* op = (uint4*)(g_t0h + (size_t)row * HID + cb);
            const uint4* bp = (const uint4*)buf;
            op[0] = bp[0]; op[1] = bp[1];
        }
    }
}

// ---------------- agg helper: chain-free gather ------------------------------
// Indices (and scales) preloaded in parallel (3/lane covers CAP=96), then
// shfl-broadcast per edge -> gathers have no load-load dependency.
template<bool EDGESCALE>
__device__ __forceinline__ float4 agg_row(int n, int lane, const float* b) {
    int cnt = g_incnt[n * PAD];
    int m = min(cnt, CAP);
    const int* row = g_esrc + n * CAP;

    int idxA = (lane < m)      ? row[lane]      : 0;
    int idxB = (lane + 32 < m) ? row[lane + 32] : 0;
    int idxC = (lane + 64 < m) ? row[lane + 64] : 0;
    float dsA = 1.f, dsB = 1.f, dsC = 1.f;
    if (EDGESCALE) {
        dsA = g_doutf[idxA];
        dsB = g_doutf[idxB];
        dsC = g_doutf[idxC];
    }

    float4 acc = make_float4(0.f, 0.f, 0.f, 0.f);
    int done = 0;
    int bidx = idxA; float bds = dsA;
#pragma unroll
    for (int batch = 0; batch < 3; batch++) {
        if (done >= m) break;
        if (batch == 1) { bidx = idxB; bds = dsB; }
        if (batch == 2) { bidx = idxC; bds = dsC; }
        int bm = min(32, m - done);
#pragma unroll 8
        for (int jj = 0; jj < bm; jj++) {
            int s = __shfl_sync(0xFFFFFFFFu, bidx, jj);
            const __half2* p = (const __half2*)(g_t0h + (size_t)s * HID + lane * 4);
            float2 v0 = __half22float2(p[0]);
            float2 v1 = __half22float2(p[1]);
            if (EDGESCALE) {
                float ds = __shfl_sync(0xFFFFFFFFu, bds, jj);
                acc.x = fmaf(ds, v0.x, acc.x); acc.y = fmaf(ds, v0.y, acc.y);
                acc.z = fmaf(ds, v1.x, acc.z); acc.w = fmaf(ds, v1.y, acc.w);
            } else {
                acc.x += v0.x; acc.y += v0.y; acc.z += v1.x; acc.w += v1.y;
            }
        }
        done += 32;
    }

    float din = inv_sqrt_deg(cnt);
    float4 bb = *(const float4*)(b + lane * 4);
    float4 o;
    o.x = fmaxf(acc.x * din + bb.x, 0.f);
    o.y = fmaxf(acc.y * din + bb.y, 0.f);
    o.z = fmaxf(acc.z * din + bb.z, 0.f);
    o.w = fmaxf(acc.w * din + bb.w, 0.f);
    return o;
}

// GraphConv1 agg (src dout scale) -> h1s = relu(.)*dout[n], fp16
__global__ void k_agg1(const float* __restrict__ b) {
    int n = (blockIdx.x * blockDim.x + threadIdx.x) >> 5;
    int lane = threadIdx.x & 31;
    if (n >= NN) return;
    float4 o = agg_row<true>(n, lane, b);
    float dn = g_doutf[n];
    __half2* hp = (__half2*)(g_h1h + (size_t)n * HID + lane * 4);
    hp[0] = __floats2half2_rn(o.x * dn, o.y * dn);
    hp[1] = __floats2half2_rn(o.z * dn, o.w * dn);
}

// GraphConv2 agg fused with el/er/w projection
__global__ void k_agg2(const float* __restrict__ b) {
    int n = (blockIdx.x * blockDim.x + threadIdx.x) >> 5;
    int lane = threadIdx.x & 31;
    if (n >= NN) return;
    float4 o = agg_row<false>(n, lane, b);
    float hr[4] = {o.x, o.y, o.z, o.w};
    float dots[12];
#pragma unroll
    for (int j = 0; j < 12; j++) {
        float s = 0.f;
#pragma unroll
        for (int i = 0; i < 4; i++) s = fmaf(hr[i], g_M[lane * 4 + i][j], s);
        dots[j] = s;
    }
#pragma unroll
    for (int off = 16; off; off >>= 1)
#pragma unroll
        for (int j = 0; j < 12; j++)
            dots[j] += __shfl_xor_sync(0xFFFFFFFFu, dots[j], off);
    if (!lane) {
        g_el4[n] = make_float4(dots[0], dots[1], dots[2], dots[3]);
        g_er4[n] = make_float4(dots[4], dots[5], dots[6], dots[7]);
        g_w4[n]  = make_float4(dots[8], dots[9], dots[10], dots[11]);
    }
}

// ---------------- fused GAT + final conv (software grid barrier) -------------
__global__ void __launch_bounds__(256) k_gatfinal(const float* __restrict__ b3,
                                                  float* __restrict__ out) {
    int lane = threadIdx.x & 31;
    int gwarp = blockIdx.x * 8 + (threadIdx.x >> 5);
    int wstride = GF_BLOCKS * 8;

    for (int d = gwarp; d < NN; d += wstride) {
        int cnt = min(g_incnt[d * PAD], CAP);
        const int* row = g_esrc + d * CAP;
        float4 er = g_er4[d];
        float erh[4] = {er.x, er.y, er.z, er.w};
        float m[4], den[4], aw[4];
#pragma unroll
        for (int h = 0; h < 4; h++) { m[h] = -INFINITY; den[h] = 0.f; aw[h] = 0.f; }
        for (int j = lane; j < cnt; j += 32) {
            int s = row[j];
            float4 el = g_el4[s];
            float4 wv = g_w4[s];
            float elh[4] = {el.x, el.y, el.z, el.w};
            float wh[4] = {wv.x, wv.y, wv.z, wv.w};
#pragma unroll
            for (int h = 0; h < 4; h++) {
                float e = elh[h] + erh[h];
                e = e > 0.f ? e : 0.2f * e;
                float mn = fmaxf(m[h], e);
                float sc = __expf(m[h] - mn);
                float p  = __expf(e - mn);
                den[h] = den[h] * sc + p;
                aw[h]  = aw[h] * sc + p * wh[h];
                m[h] = mn;
            }
        }
#pragma unroll
        for (int off = 16; off; off >>= 1) {
#pragma unroll
            for (int h = 0; h < 4; h++) {
                float m2 = __shfl_xor_sync(0xFFFFFFFFu, m[h], off);
                float d2 = __shfl_xor_sync(0xFFFFFFFFu, den[h], off);
                float a2 = __shfl_xor_sync(0xFFFFFFFFu, aw[h], off);
                float mn = fmaxf(m[h], m2);
                float s1 = (m[h] == mn) ? 1.f : __expf(m[h] - mn);
                float s2 = (m2 == mn) ? 1.f : __expf(m2 - mn);
                den[h] = den[h] * s1 + d2 * s2;
                aw[h]  = aw[h] * s1 + a2 * s2;
                m[h] = mn;
            }
        }
        if (!lane) {
            float s = g_cbg;
#pragma unroll
            for (int h = 0; h < 4; h++) s += (den[h] > 0.f) ? (aw[h] / den[h]) : 0.f;
            g_y[d] = 0.25f * s * g_doutf[d];
        }
    }

    __syncthreads();
    if (threadIdx.x == 0) {
        __threadfence();
        atomicAdd(&g_bar, 1u);
        while (atomicAdd(&g_bar, 0u) < (unsigned)GF_BLOCKS) {}
    }
    __syncthreads();

    for (int n = gwarp; n < NN; n += wstride) {
        int cnt = g_incnt[n * PAD];
        int mm = min(cnt, CAP);
        const int* row = g_esrc + n * CAP;
        float s = 0.f;
        for (int j = lane; j < mm; j += 32) s += g_y[row[j]];
#pragma unroll
        for (int o = 16; o; o >>= 1) s += __shfl_xor_sync(0xFFFFFFFFu, s, o);
        if (!lane) {
            float v = s * inv_sqrt_deg(cnt) + b3[0];
            out[n] = 1.f / (1.f + __expf(-v));
        }
    }
}

// ---------------- launch ----------------
extern "C" void kernel_launch(void* const* d_in, const int* in_sizes, int n_in,
                              void* d_out, int out_size) {
    const float* features = (const float*)d_in[0];
    const int*   src      = (const int*)d_in[1];
    const int*   dst      = (const int*)d_in[2];
    const float* W1       = (const float*)d_in[3];
    const float* b1       = (const float*)d_in[4];
    const float* W2       = (const float*)d_in[5];
    const float* b2       = (const float*)d_in[6];
    const float* W3       = (const float*)d_in[7];
    const float* b3       = (const float*)d_in[8];
    const float* Wg       = (const float*)d_in[9];
    const float* attn_l   = (const float*)d_in[10];
    const float* attn_r   = (const float*)d_in[11];
    const float* bg       = (const float*)d_in[12];
    float* out = (float*)d_out;

    static cudaStream_t s1 = nullptr;
    static cudaEvent_t ev_fork = nullptr, ev_join = nullptr;
    if (s1 == nullptr) {
        cudaStreamCreateWithFlags(&s1, cudaStreamNonBlocking);
        cudaEventCreateWithFlags(&ev_fork, cudaEventDisableTiming);
        cudaEventCreateWithFlags(&ev_join, cudaEventDisableTiming);
    }

    const int TB = 256;
    int ebl = (EE + TB - 1) / TB;
    int nwbl = (NN * 32 + TB - 1) / TB;
    int rowtiles32 = (NN + 31) / 32;     // 313

    // fork: s1 builds CSR (+prep, dout, W2 cvt); stream 0: W1 cvt -> gemm1
    cudaEventRecord(ev_fork, 0);
    cudaStreamWaitEvent(s1, ev_fork, 0);

    k_prep<<<105, 256, 0, s1>>>(Wg, attn_l, attn_r, W3, bg);
    k_build<<<ebl, TB, 0, s1>>>(src, dst);
    k_dout<<<(NN + TB - 1) / TB, TB, 0, s1>>>();
    k_wcvt2<<<16, 256, 0, s1>>>(W2);

    k_wcvt1<<<32, 256>>>(W1);
    k_gemm_mma<INF, 0><<<rowtiles32, 256>>>(features);

    cudaEventRecord(ev_join, s1);
    cudaStreamWaitEvent(0, ev_join, 0);

    // GraphConv 1 aggregation (src scale; output pre-scaled by dout, fp16)
    k_agg1<<<nwbl, TB>>>(b1);

    // GraphConv 2 (+ fused el/er/w projection)
    k_gemm_mma<HID, 1><<<rowtiles32, 256>>>(nullptr);
    k_agg2<<<nwbl, TB>>>(b2);

    // fused GAT + final conv + sigmoid (grid barrier inside)
    k_gatfinal<<<GF_BLOCKS, 256>>>(b3, out);
}

// round 15
// speedup vs baseline: 1.0823x; 1.0795x over previous
#include <cuda_runtime.h>
#include <cuda_fp16.h>
#include <mma.h>
#include <math.h>

using namespace nvcuda;

#define NN 10000
#define EE 320000
#define INF 256
#define HID 128
#define HEADS 4
#define PAD 32      // counter stride in ints -> one 128B line per counter
#define CAP 96      // max in-degree bucket capacity (Poisson(32): P(>96) ~ 1e-37)
#define GF_BLOCKS 592   // 148 SMs x 4 blocks: co-resident => spin barrier safe

// ---------------- scratch (static device globals; no allocs) ----------------
__device__ int      g_incnt[NN * PAD];
__device__ int      g_outcnt[NN * PAD];
__device__ int      g_esrc[NN * CAP];    // bucketed CSR-by-dst
__device__ float    g_doutf[NN];         // rsqrt(max(outdeg,1)) precomputed
__device__ __half   g_w1h[INF * HID];    // W1 fp16 (converted once)
__device__ __half   g_w2h[HID * HID];    // W2 fp16 (converted once)
__device__ __half   g_t0h[NN * HID];     // gemm output (pre-agg), fp16
__device__ __half   g_h1h[NN * HID];     // relu(conv1)*dout, fp16 (gemm2 input)
__device__ float4   g_el4[NN];
__device__ float4   g_er4[NN];
__device__ float4   g_w4[NN];
__device__ float    g_M[HID][12];        // folded Wg·attn_l | Wg·attn_r | Wg·W3
__device__ float    g_cbg;
__device__ float    g_y[NN];
__device__ unsigned g_bar;               // grid barrier counter (reset in k_prep)

__device__ __forceinline__ float inv_sqrt_deg(int cnt) {
    return rsqrtf(fmaxf((float)cnt, 1.f));
}

// ---------------- weight fp32->fp16 conversion (once, stream 0) --------------
__global__ void __launch_bounds__(256) k_wcvt(const float* __restrict__ W1,
                                              const float* __restrict__ W2) {
    if (blockIdx.x < 32) {
        int i4 = (blockIdx.x * 256 + threadIdx.x) * 4;
        float4 v = *(const float4*)(W1 + i4);
        __half2 h0 = __floats2half2_rn(v.x, v.y);
        __half2 h1 = __floats2half2_rn(v.z, v.w);
        uint2 u; u.x = *(unsigned*)&h0; u.y = *(unsigned*)&h1;
        *(uint2*)(g_w1h + i4) = u;
    } else {
        int i4 = ((blockIdx.x - 32) * 256 + threadIdx.x) * 4;
        float4 v = *(const float4*)(W2 + i4);
        __half2 h0 = __floats2half2_rn(v.x, v.y);
        __half2 h1 = __floats2half2_rn(v.z, v.w);
        uint2 u; u.x = *(unsigned*)&h0; u.y = *(unsigned*)&h1;
        *(uint2*)(g_w2h + i4) = u;
    }
}

// ---------------- precompute M, cbg + zero padded counters + reset barrier ---
__global__ void __launch_bounds__(256) k_prep(const float* __restrict__ Wg,
                                              const float* __restrict__ attn_l,
                                              const float* __restrict__ attn_r,
                                              const float* __restrict__ W3,
                                              const float* __restrict__ bg) {
    int lane = threadIdx.x & 31;
    if (blockIdx.x >= 65) {
        int idx = (blockIdx.x - 65) * 256 + threadIdx.x;
        if (idx < NN) { g_incnt[idx * PAD] = 0; g_outcnt[idx * PAD] = 0; }
        return;
    }
    if (blockIdx.x == 64) {
        if (threadIdx.x == 32) g_bar = 0u;
        if (threadIdx.x < 32) {
            float s = 0.f;
            for (int i = lane; i < HEADS * HID; i += 32) s += bg[i] * W3[i & (HID - 1)];
#pragma unroll
            for (int o = 16; o; o >>= 1) s += __shfl_xor_sync(0xFFFFFFFFu, s, o);
            if (!lane) g_cbg = s;
        }
        return;
    }
    int gw = blockIdx.x * 8 + (threadIdx.x >> 5);
    int k = gw >> 2, h = gw & 3;
    float sl = 0.f, sr = 0.f, sw = 0.f;
    for (int i = lane; i < HID; i += 32) {
        float wv = Wg[(size_t)k * (HEADS * HID) + h * HID + i];
        sl += wv * attn_l[h * HID + i];
        sr += wv * attn_r[h * HID + i];
        sw += wv * W3[i];
    }
#pragma unroll
    for (int o = 16; o; o >>= 1) {
        sl += __shfl_xor_sync(0xFFFFFFFFu, sl, o);
        sr += __shfl_xor_sync(0xFFFFFFFFu, sr, o);
        sw += __shfl_xor_sync(0xFFFFFFFFu, sw, o);
    }
    if (!lane) { g_M[k][h] = sl; g_M[k][4 + h] = sr; g_M[k][8 + h] = sw; }
}

// ---------------- one-pass bucketed CSR build ----------------
__global__ void k_build(const int* __restrict__ src, const int* __restrict__ dst) {
    int e = blockIdx.x * blockDim.x + threadIdx.x;
    if (e >= EE) return;
    int s = src[e], d = dst[e];
    atomicAdd(&g_outcnt[s * PAD], 1);
    int slot = atomicAdd(&g_incnt[d * PAD], 1);
    if (slot < CAP) g_esrc[d * CAP + slot] = s;
}

__global__ void k_dout() {
    int n = blockIdx.x * blockDim.x + threadIdx.x;
    if (n < NN) g_doutf[n] = inv_sqrt_deg(g_outcnt[n * PAD]);
}

// ---------------- WMMA fp16 GEMM: 32x128 tile, BK=32, 256 thr ----------------
template<int K, int SRC>
__global__ void __launch_bounds__(256) k_gemm_mma(const float* __restrict__ Aext) {
    constexpr int NIT = K / 32;
    const __half* __restrict__ Wh = (SRC == 0) ? g_w1h : g_w2h;
    __shared__ __align__(16) char smraw[16384];
    __half (*As)[40]  = reinterpret_cast<__half(*)[40]>(smraw);
    __half (*Bs)[136] = reinterpret_cast<__half(*)[136]>(smraw + 2560);
    float  (*Cs)[128] = reinterpret_cast<float(*)[128]>(smraw);

    int tid = threadIdx.x;
    int warp = tid >> 5;
    int wr = warp & 1, wc = warp >> 1;
    int row0 = blockIdx.x * 32;

    int ar = tid >> 3, akq = (tid & 7) * 4;
    int bkr = tid >> 3, bcb = (tid & 7) * 16;
    bool arow_ok = (row0 + ar) < NN;

    wmma::fragment<wmma::accumulator, 16, 16, 16, float> c0, c1;
    wmma::fill_fragment(c0, 0.f);
    wmma::fill_fragment(c1, 0.f);

    float4 aP = make_float4(0.f, 0.f, 0.f, 0.f);
    uint2  aPh = make_uint2(0, 0);
    uint4  bP0, bP1;

    auto LOAD = [&](int k0) {
        if (SRC == 0) {
            aP = arow_ok ? *(const float4*)(Aext + (size_t)(row0 + ar) * K + k0 + akq)
                         : make_float4(0.f, 0.f, 0.f, 0.f);
        } else {
            aPh = arow_ok ? *(const uint2*)(g_h1h + (size_t)(row0 + ar) * K + k0 + akq)
                          : make_uint2(0, 0);
        }
        const uint4* wp = (const uint4*)(Wh + (size_t)(k0 + bkr) * HID + bcb);
        bP0 = wp[0];
        bP1 = wp[1];
    };

    LOAD(0);
#pragma unroll
    for (int it = 0; it < NIT; it++) {
        if (it) __syncthreads();
        if (SRC == 0) {
            __half2 h0 = __floats2half2_rn(aP.x, aP.y);
            __half2 h1 = __floats2half2_rn(aP.z, aP.w);
            uint2 u; u.x = *(unsigned*)&h0; u.y = *(unsigned*)&h1;
            *(uint2*)&As[ar][akq] = u;
        } else {
            *(uint2*)&As[ar][akq] = aPh;
        }
        *(uint4*)&Bs[bkr][bcb] = bP0;
        *(uint4*)&Bs[bkr][bcb + 8] = bP1;
        __syncthreads();
        if (it + 1 < NIT) LOAD((it + 1) * 32);
#pragma unroll
        for (int kk = 0; kk < 32; kk += 16) {
            wmma::fragment<wmma::matrix_a, 16, 16, 16, __half, wmma::row_major> a;
            wmma::fragment<wmma::matrix_b, 16, 16, 16, __half, wmma::row_major> b0, b1;
            wmma::load_matrix_sync(a, &As[wr * 16][kk], 40);
            wmma::load_matrix_sync(b0, &Bs[kk][wc * 32], 136);
            wmma::load_matrix_sync(b1, &Bs[kk][wc * 32 + 16], 136);
            wmma::mma_sync(c0, a, b0, c0);
            wmma::mma_sync(c1, a, b1, c1);
        }
    }
    __syncthreads();
    wmma::store_matrix_sync(&Cs[wr * 16][wc * 32], c0, 128, wmma::mem_row_major);
    wmma::store_matrix_sync(&Cs[wr * 16][wc * 32 + 16], c1, 128, wmma::mem_row_major);
    __syncthreads();
    {
        int r = tid >> 3, cb = (tid & 7) * 16;
        int row = row0 + r;
        if (row < NN) {
            __half2 buf[8];
#pragma unroll
            for (int q = 0; q < 8; q++)
                buf[q] = __floats2half2_rn(Cs[r][cb + q * 2], Cs[r][cb + q * 2 + 1]);
            uint4* op = (uint4*)(g_t0h + (size_t)row * HID + cb);
            const uint4* bp = (const uint4*)buf;
            op[0] = bp[0]; op[1] = bp[1];
        }
    }
}

// ---------------- dual-node agg: 2 independent gather chains per warp --------
// Interleaved edge loops for nodes n0, n1 -> 2x outstanding loads per warp.
template<bool EDGESCALE>
__device__ __forceinline__ void agg_row2(int n0, int n1, int lane,
                                         const float* __restrict__ b,
                                         float4& o0, float4& o1,
                                         bool v1) {
    int m0 = min(g_incnt[n0 * PAD], CAP);
    int m1 = v1 ? min(g_incnt[n1 * PAD], CAP) : 0;
    const int* r0 = g_esrc + n0 * CAP;
    const int* r1 = g_esrc + (v1 ? n1 : n0) * CAP;
    float4 a0 = make_float4(0.f, 0.f, 0.f, 0.f);
    float4 a1 = make_float4(0.f, 0.f, 0.f, 0.f);
    int mm = max(m0, m1);
#pragma unroll 2
    for (int j = 0; j < mm; j++) {
        if (j < m0) {
            int s = r0[j];
            float ds = EDGESCALE ? g_doutf[s] : 1.f;
            const __half2* p = (const __half2*)(g_t0h + (size_t)s * HID + lane * 4);
            float2 u0 = __half22float2(p[0]);
            float2 u1 = __half22float2(p[1]);
            if (EDGESCALE) {
                a0.x = fmaf(ds, u0.x, a0.x); a0.y = fmaf(ds, u0.y, a0.y);
                a0.z = fmaf(ds, u1.x, a0.z); a0.w = fmaf(ds, u1.y, a0.w);
            } else {
                a0.x += u0.x; a0.y += u0.y; a0.z += u1.x; a0.w += u1.y;
            }
        }
        if (j < m1) {
            int s = r1[j];
            float ds = EDGESCALE ? g_doutf[s] : 1.f;
            const __half2* p = (const __half2*)(g_t0h + (size_t)s * HID + lane * 4);
            float2 u0 = __half22float2(p[0]);
            float2 u1 = __half22float2(p[1]);
            if (EDGESCALE) {
                a1.x = fmaf(ds, u0.x, a1.x); a1.y = fmaf(ds, u0.y, a1.y);
                a1.z = fmaf(ds, u1.x, a1.z); a1.w = fmaf(ds, u1.y, a1.w);
            } else {
                a1.x += u0.x; a1.y += u0.y; a1.z += u1.x; a1.w += u1.y;
            }
        }
    }
    float4 bb = *(const float4*)(b + lane * 4);
    float d0 = inv_sqrt_deg(m0);
    o0.x = fmaxf(a0.x * d0 + bb.x, 0.f);
    o0.y = fmaxf(a0.y * d0 + bb.y, 0.f);
    o0.z = fmaxf(a0.z * d0 + bb.z, 0.f);
    o0.w = fmaxf(a0.w * d0 + bb.w, 0.f);
    float d1 = inv_sqrt_deg(m1);
    o1.x = fmaxf(a1.x * d1 + bb.x, 0.f);
    o1.y = fmaxf(a1.y * d1 + bb.y, 0.f);
    o1.z = fmaxf(a1.z * d1 + bb.z, 0.f);
    o1.w = fmaxf(a1.w * d1 + bb.w, 0.f);
}

// GraphConv1 agg (src dout scale) -> h1s = relu(.)*dout[n], fp16. 2 nodes/warp.
__global__ void k_agg1(const float* __restrict__ b) {
    int w = (blockIdx.x * blockDim.x + threadIdx.x) >> 5;
    int lane = threadIdx.x & 31;
    int n0 = w * 2, n1 = w * 2 + 1;
    if (n0 >= NN) return;
    bool v1 = n1 < NN;
    float4 o0, o1;
    agg_row2<true>(n0, n1, lane, b, o0, o1, v1);
    {
        float dn = g_doutf[n0];
        __half2* hp = (__half2*)(g_h1h + (size_t)n0 * HID + lane * 4);
        hp[0] = __floats2half2_rn(o0.x * dn, o0.y * dn);
        hp[1] = __floats2half2_rn(o0.z * dn, o0.w * dn);
    }
    if (v1) {
        float dn = g_doutf[n1];
        __half2* hp = (__half2*)(g_h1h + (size_t)n1 * HID + lane * 4);
        hp[0] = __floats2half2_rn(o1.x * dn, o1.y * dn);
        hp[1] = __floats2half2_rn(o1.z * dn, o1.w * dn);
    }
}

// GraphConv2 agg fused with el/er/w projection. 2 nodes/warp.
__global__ void k_agg2(const float* __restrict__ b) {
    int w = (blockIdx.x * blockDim.x + threadIdx.x) >> 5;
    int lane = threadIdx.x & 31;
    int n0 = w * 2, n1 = w * 2 + 1;
    if (n0 >= NN) return;
    bool v1 = n1 < NN;
    float4 o0, o1;
    agg_row2<false>(n0, n1, lane, b, o0, o1, v1);

    float Mr[4][12];
#pragma unroll
    for (int i = 0; i < 4; i++)
#pragma unroll
        for (int j = 0; j < 12; j++) Mr[i][j] = g_M[lane * 4 + i][j];

    float h0[4] = {o0.x, o0.y, o0.z, o0.w};
    float h1[4] = {o1.x, o1.y, o1.z, o1.w};
    float d0[12], d1[12];
#pragma unroll
    for (int j = 0; j < 12; j++) {
        float s0 = 0.f, s1 = 0.f;
#pragma unroll
        for (int i = 0; i < 4; i++) {
            s0 = fmaf(h0[i], Mr[i][j], s0);
            s1 = fmaf(h1[i], Mr[i][j], s1);
        }
        d0[j] = s0; d1[j] = s1;
    }
#pragma unroll
    for (int off = 16; off; off >>= 1)
#pragma unroll
        for (int j = 0; j < 12; j++) {
            d0[j] += __shfl_xor_sync(0xFFFFFFFFu, d0[j], off);
            d1[j] += __shfl_xor_sync(0xFFFFFFFFu, d1[j], off);
        }
    if (!lane) {
        g_el4[n0] = make_float4(d0[0], d0[1], d0[2], d0[3]);
        g_er4[n0] = make_float4(d0[4], d0[5], d0[6], d0[7]);
        g_w4[n0]  = make_float4(d0[8], d0[9], d0[10], d0[11]);
        if (v1) {
            g_el4[n1] = make_float4(d1[0], d1[1], d1[2], d1[3]);
            g_er4[n1] = make_float4(d1[4], d1[5], d1[6], d1[7]);
            g_w4[n1]  = make_float4(d1[8], d1[9], d1[10], d1[11]);
        }
    }
}

// ---------------- fused GAT + final conv (software grid barrier) -------------
__global__ void __launch_bounds__(256) k_gatfinal(const float* __restrict__ b3,
                                                  float* __restrict__ out) {
    int lane = threadIdx.x & 31;
    int gwarp = blockIdx.x * 8 + (threadIdx.x >> 5);
    int wstride = GF_BLOCKS * 8;

    for (int d = gwarp; d < NN; d += wstride) {
        int cnt = min(g_incnt[d * PAD], CAP);
        const int* row = g_esrc + d * CAP;
        float4 er = g_er4[d];
        float erh[4] = {er.x, er.y, er.z, er.w};
        float m[4], den[4], aw[4];
#pragma unroll
        for (int h = 0; h < 4; h++) { m[h] = -INFINITY; den[h] = 0.f; aw[h] = 0.f; }
        for (int j = lane; j < cnt; j += 32) {
            int s = row[j];
            float4 el = g_el4[s];
            float4 wv = g_w4[s];
            float elh[4] = {el.x, el.y, el.z, el.w};
            float wh[4] = {wv.x, wv.y, wv.z, wv.w};
#pragma unroll
            for (int h = 0; h < 4; h++) {
                float e = elh[h] + erh[h];
                e = e > 0.f ? e : 0.2f * e;
                float mn = fmaxf(m[h], e);
                float sc = __expf(m[h] - mn);
                float p  = __expf(e - mn);
                den[h] = den[h] * sc + p;
                aw[h]  = aw[h] * sc + p * wh[h];
                m[h] = mn;
            }
        }
#pragma unroll
        for (int off = 16; off; off >>= 1) {
#pragma unroll
            for (int h = 0; h < 4; h++) {
                float m2 = __shfl_xor_sync(0xFFFFFFFFu, m[h], off);
                float d2 = __shfl_xor_sync(0xFFFFFFFFu, den[h], off);
                float a2 = __shfl_xor_sync(0xFFFFFFFFu, aw[h], off);
                float mn = fmaxf(m[h], m2);
                float s1 = (m[h] == mn) ? 1.f : __expf(m[h] - mn);
                float s2 = (m2 == mn) ? 1.f : __expf(m2 - mn);
                den[h] = den[h] * s1 + d2 * s2;
                aw[h]  = aw[h] * s1 + a2 * s2;
                m[h] = mn;
            }
        }
        if (!lane) {
            float s = g_cbg;
#pragma unroll
            for (int h = 0; h < 4; h++) s += (den[h] > 0.f) ? (aw[h] / den[h]) : 0.f;
            g_y[d] = 0.25f * s * g_doutf[d];
        }
    }

    __syncthreads();
    if (threadIdx.x == 0) {
        __threadfence();
        atomicAdd(&g_bar, 1u);
        while (atomicAdd(&g_bar, 0u) < (unsigned)GF_BLOCKS) {}
    }
    __syncthreads();

    for (int n = gwarp; n < NN; n += wstride) {
        int cnt = g_incnt[n * PAD];
        int mm = min(cnt, CAP);
        const int* row = g_esrc + n * CAP;
        float s = 0.f;
        for (int j = lane; j < mm; j += 32) s += g_y[row[j]];
#pragma unroll
        for (int o = 16; o; o >>= 1) s += __shfl_xor_sync(0xFFFFFFFFu, s, o);
        if (!lane) {
            float v = s * inv_sqrt_deg(cnt) + b3[0];
            out[n] = 1.f / (1.f + __expf(-v));
        }
    }
}

// ---------------- launch ----------------
extern "C" void kernel_launch(void* const* d_in, const int* in_sizes, int n_in,
                              void* d_out, int out_size) {
    const float* features = (const float*)d_in[0];
    const int*   src      = (const int*)d_in[1];
    const int*   dst      = (const int*)d_in[2];
    const float* W1       = (const float*)d_in[3];
    const float* b1       = (const float*)d_in[4];
    const float* W2       = (const float*)d_in[5];
    const float* b2       = (const float*)d_in[6];
    const float* W3       = (const float*)d_in[7];
    const float* b3       = (const float*)d_in[8];
    const float* Wg       = (const float*)d_in[9];
    const float* attn_l   = (const float*)d_in[10];
    const float* attn_r   = (const float*)d_in[11];
    const float* bg       = (const float*)d_in[12];
    float* out = (float*)d_out;

    static cudaStream_t s1 = nullptr;
    static cudaEvent_t ev_fork = nullptr, ev_join = nullptr;
    if (s1 == nullptr) {
        cudaStreamCreateWithFlags(&s1, cudaStreamNonBlocking);
        cudaEventCreateWithFlags(&ev_fork, cudaEventDisableTiming);
        cudaEventCreateWithFlags(&ev_join, cudaEventDisableTiming);
    }

    const int TB = 256;
    int ebl = (EE + TB - 1) / TB;
    int nwbl2 = ((NN + 1) / 2 * 32 + TB - 1) / TB;   // 2 nodes per warp: 625
    int rowtiles32 = (NN + 31) / 32;                 // 313

    // fork: s1 builds bucketed CSR (+prep, dout); stream 0: wcvt -> gemm1
    cudaEventRecord(ev_fork, 0);
    cudaStreamWaitEvent(s1, ev_fork, 0);

    k_prep<<<105, 256, 0, s1>>>(Wg, attn_l, attn_r, W3, bg);
    k_build<<<ebl, TB, 0, s1>>>(src, dst);
    k_dout<<<(NN + TB - 1) / TB, TB, 0, s1>>>();

    k_wcvt<<<48, 256>>>(W1, W2);
    k_gemm_mma<INF, 0><<<rowtiles32, 256>>>(features);

    cudaEventRecord(ev_join, s1);
    cudaStreamWaitEvent(0, ev_join, 0);

    // GraphConv 1 aggregation (src scale; output pre-scaled by dout, fp16)
    k_agg1<<<nwbl2, TB>>>(b1);

    // GraphConv 2 (+ fused el/er/w projection)
    k_gemm_mma<HID, 1><<<rowtiles32, 256>>>(nullptr);
    k_agg2<<<nwbl2, TB>>>(b2);

    // fused GAT + final conv + sigmoid (grid barrier inside)
    k_gatfinal<<<GF_BLOCKS, 256>>>(b3, out);
}